// round 12
// baseline (speedup 1.0000x reference)
#include <cuda_runtime.h>
#include <cuda_bf16.h>
#include <math.h>
#include <stdint.h>

#define SLOPE 0.01f
constexpr float RCOEF = 1.0f - SLOPE;

// -------- problem constants --------
constexpr int Dd    = 32;
constexpr int Hh    = 128;
constexpr int Bb    = 64;
constexpr int Tt    = 514;
constexpr int TTt   = 512;
constexpr int NTOT  = Bb * TTt;          // 32768
constexpr int NTILE = 128;
constexpr int NTILES = NTOT / NTILE;     // 256

// output layout (reference return order, concatenated)
constexpr size_t RES_OFF  = 0;                        // (64,512,32)
constexpr size_t SUM_OFF  = (size_t)Bb * TTt * Dd;    // (64,)
constexpr size_t HIST_OFF = SUM_OFF + Bb;             // (32,32768,1,64)

// -------- shared offsets (u32 units) — 59 KB, 3 CTAs/SM --------
constexpr int XWS   = 36;                // x-window row stride
constexpr int W1TS  = 132;               // transposed W1 row stride (k rows, 128 permuted h cols)
constexpr int O_XW    = 0;                               // 130*36 = 4680 (reused as u_hi later)
constexpr int O_W1T   = 4680;                            // 64*132 = 8448 (<= old 8704 region; reused as u_lo later)
constexpr int O_MASK  = 13384;                           // 128*4
constexpr int O_S     = 13896;                           // 64
constexpr int O_WLAST = 13960;                           // 128
constexpr int O_B1    = 14088;                           // 128
constexpr int O_W2    = 14216;                           // 128
constexpr int O_YY    = 14344;                           // 132
constexpr int O_RS    = 14476;                           // 128
constexpr int O_JS    = 14604;                           // 128
constexpr int O_RED   = 14732;                           // 4
constexpr int SMEM_U32 = 14736;
constexpr int SMEM_BYTES = SMEM_U32 * 4;                 // 58944

// u_* packed arrays (reusing dead regions): [k'=0..63][h_pair=0..63], stride 68
constexpr int O_UH = O_XW;    // 4352 <= 4680
constexpr int O_UL = O_W1T;   // 4352 <= 8448
constexpr int UST  = 68;

// permuted column of h within W1T rows: consecutive j for fixed (lr)
__device__ __forceinline__ int hperm(int h) { return (h & 7) * 16 + (h >> 3); }

// CUTLASS-style fast 3xTF32 split: hi = truncate-to-tf32 (LOP3), lo = exact tail (FADD).
__device__ __forceinline__ void split_fast(float v, uint32_t& hi, uint32_t& lo) {
    hi = __float_as_uint(v) & 0xFFFFE000u;
    lo = __float_as_uint(v - __uint_as_float(hi));
}

__device__ __forceinline__ void mma8(float* d, const uint32_t* a, uint32_t b0, uint32_t b1) {
    asm volatile(
        "mma.sync.aligned.m16n8k8.row.col.f32.tf32.tf32.f32 "
        "{%0,%1,%2,%3}, {%4,%5,%6,%7}, {%8,%9}, {%0,%1,%2,%3};"
        : "+f"(d[0]), "+f"(d[1]), "+f"(d[2]), "+f"(d[3])
        : "r"(a[0]), "r"(a[1]), "r"(a[2]), "r"(a[3]), "r"(b0), "r"(b1));
}
__device__ __forceinline__ void mma16bf(float* d, const uint32_t* a, uint32_t b0, uint32_t b1) {
    asm volatile(
        "mma.sync.aligned.m16n8k16.row.col.f32.bf16.bf16.f32 "
        "{%0,%1,%2,%3}, {%4,%5,%6,%7}, {%8,%9}, {%0,%1,%2,%3};"
        : "+f"(d[0]), "+f"(d[1]), "+f"(d[2]), "+f"(d[3])
        : "r"(a[0]), "r"(a[1]), "r"(a[2]), "r"(a[3]), "r"(b0), "r"(b1));
}

// 2 mask bits -> bf16x2 {1.0|0.0, 1.0|0.0}; low half = lower h (bit0)
__device__ __forceinline__ uint32_t mask2bf(uint32_t p) {
    return (p & 1u) * 0x3F80u | (p & 2u) * 0x1FC00000u;
}

__global__ void zero_sum_kernel(float* out) { out[SUM_OFF + threadIdx.x] = 0.0f; }

extern __shared__ uint32_t smemu[];

__global__ __launch_bounds__(256, 3)
void fused_mma(const float* __restrict__ x,  const float* __restrict__ W1,
               const float* __restrict__ b1, const float* __restrict__ W2,
               const float* __restrict__ b2, float* __restrict__ out)
{
    float* sf = (float*)smemu;
    const int tid  = threadIdx.x;
    const int lane = tid & 31;
    const int w    = tid >> 5;
    const int lr   = lane >> 2;   // 0..7
    const int lc   = lane & 3;    // 0..3

    const int d  = blockIdx.x;
    const int n0 = blockIdx.y * NTILE;
    const int bb = n0 / TTt;
    const int t0 = n0 % TTt;

    // ---------------- preamble ----------------
    {
        const float* W1g = W1 + (size_t)d * Hh * 65;
        for (int idx = tid; idx < Hh * 65; idx += 256) {
            int h = idx / 65;
            int k = idx - h * 65;
            float v = W1g[idx];
            if (k == 64) sf[O_WLAST + h] = v;
            else         sf[O_W1T + k * W1TS + hperm(h)] = v;
        }
        const float* xg = x + ((size_t)bb * Tt + t0) * Dd;
        for (int idx = tid; idx < 130 * 32; idx += 256) {
            int r = idx >> 5, c = idx & 31;
            float v = xg[idx];
            sf[O_XW + r * XWS + c] = v;
            if (c == d) sf[O_YY + r] = v;
        }
        if (tid < 128) {
            sf[O_B1 + tid] = b1[(size_t)d * Hh + tid];
            sf[O_W2 + tid] = W2[(size_t)d * Hh + tid];
            sf[O_RS + tid] = 0.0f;
            sf[O_JS + tid] = 0.0f;
        }
        if (tid == 0) sf[O_RED] = 0.0f;
    }
    __syncthreads();

    // colsums S[k] = sum_h w2[h]*W1[h][k]  (via transposed-permuted W1T)
    if (tid < 64) {
        float s = 0.0f;
        #pragma unroll 8
        for (int col = 0; col < 128; col++) {
            const int h = (col & 15) * 8 + (col >> 4);
            s = fmaf(sf[O_W2 + h], sf[O_W1T + tid * W1TS + col], s);
        }
        sf[O_S + tid] = s;
    }

    // ---------------- GEMM A: pre = XX @ W1[:, :64]^T (3xTF32), two 16-row passes --------
    const int nblk = (w & 3) * 32;
    const int hblk = (w >> 2) * 64;
    const int hb3  = hblk >> 3;

    #pragma unroll 1
    for (int pass = 0; pass < 2; pass++) {
        const int rbase = nblk + 16 * pass;

        float acc[8][4];
        #pragma unroll
        for (int j = 0; j < 8; j++)
            #pragma unroll
            for (int q = 0; q < 4; q++) acc[j][q] = 0.0f;

        #pragma unroll 2
        for (int s = 0; s < 8; s++) {
            const int l  = s >> 2;
            const int c0 = ((8 * s) & 31) + lc;
            uint32_t ah[4], al[4];
            {
                int base = O_XW + (rbase + lr + l) * XWS + c0;
                split_fast(sf[base],               ah[0], al[0]);
                split_fast(sf[base + 8 * XWS],     ah[1], al[1]);
                split_fast(sf[base + 4],           ah[2], al[2]);
                split_fast(sf[base + 8 * XWS + 4], ah[3], al[3]);
            }
            // B side: 4x LDS.128 covers all 8 j fragments (both k rows)
            const int ra = O_W1T + (8 * s + lc) * W1TS + lr * 16 + hb3;
            float4 q0 = *(const float4*)&sf[ra];              // k=8s+lc,   j=0..3
            float4 q1 = *(const float4*)&sf[ra + 4];          // k=8s+lc,   j=4..7
            float4 q2 = *(const float4*)&sf[ra + 4 * W1TS];   // k=8s+lc+4, j=0..3
            float4 q3 = *(const float4*)&sf[ra + 4 * W1TS + 4];
            const float* b0p = &q0.x;
            const float* b1p = &q2.x;
            #pragma unroll
            for (int j = 0; j < 4; j++) {
                uint32_t bh0, bl0, bh1, bl1;
                split_fast(b0p[j], bh0, bl0);
                split_fast(b1p[j], bh1, bl1);
                mma8(acc[j], ah, bh0, bh1);
                mma8(acc[j], ah, bl0, bl1);
                mma8(acc[j], al, bh0, bh1);
            }
            const float* b2p = &q1.x;
            const float* b3p = &q3.x;
            #pragma unroll
            for (int j = 0; j < 4; j++) {
                uint32_t bh0, bl0, bh1, bl1;
                split_fast(b2p[j], bh0, bl0);
                split_fast(b3p[j], bh1, bl1);
                mma8(acc[j + 4], ah, bh0, bh1);
                mma8(acc[j + 4], ah, bl0, bl1);
                mma8(acc[j + 4], al, bh0, bh1);
            }
        }

        // epilogue for this pass
        {
            float yyv[2], rp[2] = {0.0f, 0.0f}, jp[2] = {0.0f, 0.0f};
            uint32_t mm0[2] = {0u, 0u}, mm1[2] = {0u, 0u};
            #pragma unroll
            for (int ci = 0; ci < 2; ci++)
                yyv[ci] = sf[O_YY + rbase + 8 * ci + lr + 2];

            #pragma unroll
            for (int j = 0; j < 8; j++) {
                #pragma unroll
                for (int cj = 0; cj < 2; cj++) {
                    const int h = hblk + 8 * j + 2 * lc + cj;
                    const float wl = sf[O_WLAST + h];
                    const float bv = sf[O_B1 + h];
                    const float w2 = sf[O_W2 + h];
                    const uint32_t bitv = 1u << (8 * (j & 3) + 2 * lc + cj);
                    #pragma unroll
                    for (int ci = 0; ci < 2; ci++) {
                        float pre = fmaf(yyv[ci], wl, acc[j][2 * ci + cj]) + bv;
                        float gv = (pre >= 0.0f) ? w2 : SLOPE * w2;
                        rp[ci] = fmaf(pre, gv, rp[ci]);
                        jp[ci] = fmaf(gv, wl, jp[ci]);
                        uint32_t bit = (pre >= 0.0f) ? bitv : 0u;
                        if (j < 4) mm0[ci] |= bit; else mm1[ci] |= bit;
                    }
                }
            }
            #pragma unroll
            for (int ci = 0; ci < 2; ci++) {
                const int row = rbase + 8 * ci + lr;
                uint32_t m0 = mm0[ci], m1 = mm1[ci];
                float rpv = rp[ci], jpv = jp[ci];
                m0 |= __shfl_xor_sync(0xffffffffu, m0, 1);
                m0 |= __shfl_xor_sync(0xffffffffu, m0, 2);
                m1 |= __shfl_xor_sync(0xffffffffu, m1, 1);
                m1 |= __shfl_xor_sync(0xffffffffu, m1, 2);
                rpv += __shfl_xor_sync(0xffffffffu, rpv, 1);
                rpv += __shfl_xor_sync(0xffffffffu, rpv, 2);
                jpv += __shfl_xor_sync(0xffffffffu, jpv, 1);
                jpv += __shfl_xor_sync(0xffffffffu, jpv, 2);
                if (lc == 0) {
                    smemu[O_MASK + row * 4 + (hblk >> 5)]     = m0;
                    smemu[O_MASK + row * 4 + (hblk >> 5) + 1] = m1;
                    atomicAdd(&sf[O_RS + row], rpv);
                    atomicAdd(&sf[O_JS + row], jpv);
                }
            }
        }
    }
    __syncthreads();

    // residual + logdet outputs
    if (tid < 128) {
        const int n = tid;
        out[RES_OFF + ((size_t)(bb * TTt + t0 + n)) * Dd + d] = sf[O_RS + n] + __ldg(&b2[d]);
        float ls = logf(fabsf(sf[O_JS + n]));
        #pragma unroll
        for (int o = 16; o; o >>= 1) ls += __shfl_down_sync(0xffffffffu, ls, o);
        if (lane == 0) atomicAdd(&sf[O_RED], ls);
    }

    // ---------------- build u = w2 .* W1 as packed bf16 hi/lo --------------------
    uint32_t lo_st[16];
    #pragma unroll
    for (int t = 0; t < 16; t++) {
        const int idx = tid + 256 * t;          // 0..4095
        const int k = idx >> 6, hp = idx & 63;
        const int h0 = 2 * hp, h1 = 2 * hp + 1;
        const float u0 = sf[O_W1T + k * W1TS + hperm(h0)] * sf[O_W2 + h0];
        const float u1 = sf[O_W1T + k * W1TS + hperm(h1)] * sf[O_W2 + h1];
        __nv_bfloat162 hi2 = __floats2bfloat162_rn(u0, u1);   // .x (low) = even h
        smemu[O_UH + k * UST + hp] = *(uint32_t*)&hi2;
        const float l0 = u0 - __bfloat162float(hi2.x);
        const float l1 = u1 - __bfloat162float(hi2.y);
        __nv_bfloat162 lo2 = __floats2bfloat162_rn(l0, l1);
        lo_st[t] = *(uint32_t*)&lo2;
    }
    __syncthreads();   // all W1T reads complete before overwrite
    #pragma unroll
    for (int t = 0; t < 16; t++) {
        const int idx = tid + 256 * t;
        const int k = idx >> 6, hp = idx & 63;
        smemu[O_UL + k * UST + hp] = lo_st[t];
    }
    __syncthreads();

    // ---------------- GEMM B: jac = SLOPE*S + RCOEF*(mask @ u)  (bf16 hi+lo, k16) -------
    const int nblk2 = (w & 3) * 32;
    const int kblk  = (w >> 2) * 32;

    float acc2[2][4][4];
    #pragma unroll
    for (int i = 0; i < 2; i++)
        #pragma unroll
        for (int j = 0; j < 4; j++)
            #pragma unroll
            for (int q = 0; q < 4; q++) acc2[i][j][q] = 0.0f;

    #pragma unroll 2
    for (int step = 0; step < 8; step++) {
        const int mw    = step >> 1;
        const int shift = (step & 1) * 16 + 2 * lc;
        uint32_t a[2][4];
        #pragma unroll
        for (int i = 0; i < 2; i++) {
            const uint32_t mLo = smemu[O_MASK + (nblk2 + 16 * i + lr) * 4 + mw];
            const uint32_t mHi = smemu[O_MASK + (nblk2 + 16 * i + lr + 8) * 4 + mw];
            a[i][0] = mask2bf((mLo >> shift) & 3u);
            a[i][1] = mask2bf((mHi >> shift) & 3u);
            a[i][2] = mask2bf((mLo >> (shift + 8)) & 3u);
            a[i][3] = mask2bf((mHi >> (shift + 8)) & 3u);
        }
        const int hp0 = 8 * step + lc;
        #pragma unroll
        for (int j = 0; j < 4; j++) {
            const int kp = kblk + 8 * j + lr;
            const uint32_t bh0 = smemu[O_UH + kp * UST + hp0];
            const uint32_t bh1 = smemu[O_UH + kp * UST + hp0 + 4];
            const uint32_t bl0 = smemu[O_UL + kp * UST + hp0];
            const uint32_t bl1 = smemu[O_UL + kp * UST + hp0 + 4];
            #pragma unroll
            for (int i = 0; i < 2; i++) {
                mma16bf(acc2[i][j], a[i], bh0, bh1);
                mma16bf(acc2[i][j], a[i], bl0, bl1);
            }
        }
    }

    // write hist_jac: jac = SLOPE*S[k] + RCOEF*acc2
    #pragma unroll
    for (int i = 0; i < 2; i++) {
        #pragma unroll
        for (int ci = 0; ci < 2; ci++) {
            const int r = nblk2 + 16 * i + 8 * ci + lr;
            float* hb = out + HIST_OFF + ((size_t)d * NTOT + n0 + r) * 64;
            #pragma unroll
            for (int j = 0; j < 4; j++) {
                const int col = kblk + 8 * j + 2 * lc;
                const float s0 = sf[O_S + col];
                const float s1 = sf[O_S + col + 1];
                float2 v = make_float2(fmaf(RCOEF, acc2[i][j][2 * ci],     SLOPE * s0),
                                       fmaf(RCOEF, acc2[i][j][2 * ci + 1], SLOPE * s1));
                *(float2*)(hb + col) = v;
            }
        }
    }

    __syncthreads();
    if (tid == 0) atomicAdd(&out[SUM_OFF + bb], sf[O_RED]);
}

extern "C" void kernel_launch(void* const* d_in, const int* in_sizes, int n_in,
                              void* d_out, int out_size) {
    const float* x  = (const float*)d_in[0];
    const float* W1 = (const float*)d_in[1];
    const float* b1 = (const float*)d_in[2];
    const float* W2 = (const float*)d_in[3];
    const float* b2 = (const float*)d_in[4];
    float* out = (float*)d_out;

    cudaFuncSetAttribute(fused_mma, cudaFuncAttributeMaxDynamicSharedMemorySize, SMEM_BYTES);

    zero_sum_kernel<<<1, Bb>>>(out);
    fused_mma<<<dim3(Dd, NTILES), 256, SMEM_BYTES>>>(x, W1, b1, W2, b2, out);
}

// round 13
// speedup vs baseline: 1.0041x; 1.0041x over previous
#include <cuda_runtime.h>
#include <cuda_bf16.h>
#include <math.h>
#include <stdint.h>

#define SLOPE 0.01f
constexpr float RCOEF = 1.0f - SLOPE;

// -------- problem constants --------
constexpr int Dd    = 32;
constexpr int Hh    = 128;
constexpr int Bb    = 64;
constexpr int Tt    = 514;
constexpr int TTt   = 512;
constexpr int NTOT  = Bb * TTt;          // 32768
constexpr int NTILE = 128;
constexpr int NTILES = NTOT / NTILE;     // 256

// output layout (reference return order, concatenated)
constexpr size_t RES_OFF  = 0;                        // (64,512,32)
constexpr size_t SUM_OFF  = (size_t)Bb * TTt * Dd;    // (64,)
constexpr size_t HIST_OFF = SUM_OFF + Bb;             // (32,32768,1,64)

// -------- shared offsets (u32 units) — ~59.5 KB, 3 CTAs/SM --------
constexpr int XWS = 36;                  // x-window row stride
constexpr int W1S = 68;                  // W1 row stride (row-major h x k)
constexpr int O_XW    = 0;                               // 130*36 = 4680 (reused as u_hi later)
constexpr int O_W1    = 4680;                            // 128*68 = 8704 (reused as u_lo later)
constexpr int O_MASK  = 13384;                           // 128*4
constexpr int O_S     = 13896;                           // 64
constexpr int O_WBW   = 13960;                           // 128*4: {w1last, b1, w2, pad}
constexpr int O_YY    = 14472;                           // 132
constexpr int O_RS    = 14604;                           // 128
constexpr int O_JS    = 14732;                           // 128
constexpr int O_RED   = 14860;                           // 4
constexpr int SMEM_U32 = 14864;
constexpr int SMEM_BYTES = SMEM_U32 * 4;                 // 59456

// u_* packed arrays (reusing dead regions): [k'=0..63][h_pair=0..63], stride 68
constexpr int O_UH = O_XW;    // 4352 <= 4680
constexpr int O_UL = O_W1;    // 4352 <= 8704
constexpr int UST  = 68;

// CUTLASS-style fast 3xTF32 split: hi = truncate-to-tf32 (LOP3), lo = exact tail (FADD).
__device__ __forceinline__ void split_fast(float v, uint32_t& hi, uint32_t& lo) {
    hi = __float_as_uint(v) & 0xFFFFE000u;
    lo = __float_as_uint(v - __uint_as_float(hi));
}

__device__ __forceinline__ void mma8(float* d, const uint32_t* a, uint32_t b0, uint32_t b1) {
    asm volatile(
        "mma.sync.aligned.m16n8k8.row.col.f32.tf32.tf32.f32 "
        "{%0,%1,%2,%3}, {%4,%5,%6,%7}, {%8,%9}, {%0,%1,%2,%3};"
        : "+f"(d[0]), "+f"(d[1]), "+f"(d[2]), "+f"(d[3])
        : "r"(a[0]), "r"(a[1]), "r"(a[2]), "r"(a[3]), "r"(b0), "r"(b1));
}
__device__ __forceinline__ void mma16bf(float* d, const uint32_t* a, uint32_t b0, uint32_t b1) {
    asm volatile(
        "mma.sync.aligned.m16n8k16.row.col.f32.bf16.bf16.f32 "
        "{%0,%1,%2,%3}, {%4,%5,%6,%7}, {%8,%9}, {%0,%1,%2,%3};"
        : "+f"(d[0]), "+f"(d[1]), "+f"(d[2]), "+f"(d[3])
        : "r"(a[0]), "r"(a[1]), "r"(a[2]), "r"(a[3]), "r"(b0), "r"(b1));
}

// 2 mask bits -> bf16x2 {1.0|0.0, 1.0|0.0}; low half = lower h (bit0)
__device__ __forceinline__ uint32_t mask2bf(uint32_t p) {
    return (p & 1u) * 0x3F80u | (p & 2u) * 0x1FC00000u;
}

__global__ void zero_sum_kernel(float* out) { out[SUM_OFF + threadIdx.x] = 0.0f; }

extern __shared__ uint32_t smemu[];

__global__ __launch_bounds__(256, 3)
void fused_mma(const float* __restrict__ x,  const float* __restrict__ W1,
               const float* __restrict__ b1, const float* __restrict__ W2,
               const float* __restrict__ b2, float* __restrict__ out)
{
    float* sf = (float*)smemu;
    const int tid  = threadIdx.x;
    const int lane = tid & 31;
    const int w    = tid >> 5;
    const int lr   = lane >> 2;   // 0..7
    const int lc   = lane & 3;    // 0..3

    const int d  = blockIdx.x;
    const int n0 = blockIdx.y * NTILE;
    const int bb = n0 / TTt;
    const int t0 = n0 % TTt;

    // ---------------- preamble ----------------
    {
        const float* W1g = W1 + (size_t)d * Hh * 65;
        for (int idx = tid; idx < Hh * 65; idx += 256) {
            int h = idx / 65;
            int k = idx - h * 65;
            float v = W1g[idx];
            if (k == 64) sf[O_WBW + 4 * h] = v;       // w1last
            else         sf[O_W1 + h * W1S + k] = v;
        }
        const float* xg = x + ((size_t)bb * Tt + t0) * Dd;
        for (int idx = tid; idx < 130 * 32; idx += 256) {
            int r = idx >> 5, c = idx & 31;
            float v = xg[idx];
            sf[O_XW + r * XWS + c] = v;
            if (c == d) sf[O_YY + r] = v;
        }
        if (tid < 128) {
            sf[O_WBW + 4 * tid + 1] = b1[(size_t)d * Hh + tid];
            sf[O_WBW + 4 * tid + 2] = W2[(size_t)d * Hh + tid];
            sf[O_RS + tid] = 0.0f;
            sf[O_JS + tid] = 0.0f;
        }
        if (tid == 0) sf[O_RED] = 0.0f;
    }
    __syncthreads();

    // colsums S[k] = sum_h w2[h]*W1[h][k]
    if (tid < 64) {
        float s = 0.0f;
        #pragma unroll 8
        for (int h = 0; h < Hh; h++)
            s = fmaf(sf[O_WBW + 4 * h + 2], sf[O_W1 + h * W1S + tid], s);
        sf[O_S + tid] = s;
    }

    // ---------------- GEMM A: pre = XX @ W1[:, :64]^T (3xTF32), two 32-h passes --------
    // warp tile 32n x 64h, split along h: pass covers 32n x 32h (acc = 32 regs)
    const int nblk = (w & 3) * 32;
    const int hgrp = (w >> 2);     // 0 or 1

    float rp[2][2] = {{0.0f, 0.0f}, {0.0f, 0.0f}};
    float jp[2][2] = {{0.0f, 0.0f}, {0.0f, 0.0f}};

    #pragma unroll 1
    for (int pass = 0; pass < 2; pass++) {
        const int hb = hgrp * 64 + pass * 32;

        float acc[2][4][4];
        #pragma unroll
        for (int i = 0; i < 2; i++)
            #pragma unroll
            for (int j = 0; j < 4; j++)
                #pragma unroll
                for (int q = 0; q < 4; q++) acc[i][j][q] = 0.0f;

        #pragma unroll 2
        for (int s = 0; s < 8; s++) {
            const int l  = s >> 2;
            const int c0 = ((8 * s) & 31) + lc;
            uint32_t ah[2][4], al[2][4];
            #pragma unroll
            for (int i = 0; i < 2; i++) {
                int base = O_XW + (nblk + 16 * i + lr + l) * XWS + c0;
                split_fast(sf[base],               ah[i][0], al[i][0]);
                split_fast(sf[base + 8 * XWS],     ah[i][1], al[i][1]);
                split_fast(sf[base + 4],           ah[i][2], al[i][2]);
                split_fast(sf[base + 8 * XWS + 4], ah[i][3], al[i][3]);
            }
            #pragma unroll
            for (int j = 0; j < 4; j++) {
                int hrow = O_W1 + (hb + 8 * j + lr) * W1S + 8 * s + lc;
                uint32_t bh0, bl0, bh1, bl1;
                split_fast(sf[hrow],     bh0, bl0);
                split_fast(sf[hrow + 4], bh1, bl1);
                #pragma unroll
                for (int i = 0; i < 2; i++) {
                    mma8(acc[i][j], ah[i], bh0, bh1);
                    mma8(acc[i][j], ah[i], bl0, bl1);
                    mma8(acc[i][j], al[i], bh0, bh1);
                }
            }
        }

        // epilogue for this h-pass: mask word per row; rp/jp accumulate across passes
        #pragma unroll
        for (int i = 0; i < 2; i++) {
            #pragma unroll
            for (int ci = 0; ci < 2; ci++) {
                const int row = nblk + 16 * i + 8 * ci + lr;
                const float yyv = sf[O_YY + row + 2];
                uint32_t m = 0;
                #pragma unroll
                for (int j = 0; j < 4; j++) {
                    #pragma unroll
                    for (int cj = 0; cj < 2; cj++) {
                        const int h = hb + 8 * j + 2 * lc + cj;
                        const float4 wbw = *(const float4*)&sf[O_WBW + 4 * h];
                        // wbw.x = w1last, wbw.y = b1, wbw.z = w2
                        float pre = fmaf(yyv, wbw.x, acc[i][j][2 * ci + cj]) + wbw.y;
                        float gv = (pre >= 0.0f) ? wbw.z : SLOPE * wbw.z;
                        rp[i][ci] = fmaf(pre, gv, rp[i][ci]);
                        jp[i][ci] = fmaf(gv, wbw.x, jp[i][ci]);
                        if (pre >= 0.0f) m |= 1u << (8 * j + 2 * lc + cj);
                    }
                }
                m |= __shfl_xor_sync(0xffffffffu, m, 1);
                m |= __shfl_xor_sync(0xffffffffu, m, 2);
                if (lc == 0)
                    smemu[O_MASK + row * 4 + 2 * hgrp + pass] = m;
            }
        }
    }

    // rp/jp reductions (summed over both h-passes)
    #pragma unroll
    for (int i = 0; i < 2; i++) {
        #pragma unroll
        for (int ci = 0; ci < 2; ci++) {
            const int row = nblk + 16 * i + 8 * ci + lr;
            float rpv = rp[i][ci], jpv = jp[i][ci];
            rpv += __shfl_xor_sync(0xffffffffu, rpv, 1);
            rpv += __shfl_xor_sync(0xffffffffu, rpv, 2);
            jpv += __shfl_xor_sync(0xffffffffu, jpv, 1);
            jpv += __shfl_xor_sync(0xffffffffu, jpv, 2);
            if (lc == 0) {
                atomicAdd(&sf[O_RS + row], rpv);
                atomicAdd(&sf[O_JS + row], jpv);
            }
        }
    }
    __syncthreads();

    // residual + logdet outputs
    if (tid < 128) {
        const int n = tid;
        out[RES_OFF + ((size_t)(bb * TTt + t0 + n)) * Dd + d] = sf[O_RS + n] + __ldg(&b2[d]);
        float ls = logf(fabsf(sf[O_JS + n]));
        #pragma unroll
        for (int o = 16; o; o >>= 1) ls += __shfl_down_sync(0xffffffffu, ls, o);
        if (lane == 0) atomicAdd(&sf[O_RED], ls);
    }

    // ---------------- build u = w2 .* W1 as packed bf16 hi/lo --------------------
    uint32_t lo_st[16];
    #pragma unroll
    for (int t = 0; t < 16; t++) {
        const int idx = tid + 256 * t;          // 0..4095
        const int k = idx >> 6, hp = idx & 63;
        const int h0 = 2 * hp, h1 = 2 * hp + 1;
        const float u0 = sf[O_W1 + h0 * W1S + k] * sf[O_WBW + 4 * h0 + 2];
        const float u1 = sf[O_W1 + h1 * W1S + k] * sf[O_WBW + 4 * h1 + 2];
        __nv_bfloat162 hi2 = __floats2bfloat162_rn(u0, u1);   // .x (low) = even h
        smemu[O_UH + k * UST + hp] = *(uint32_t*)&hi2;
        const float l0 = u0 - __bfloat162float(hi2.x);
        const float l1 = u1 - __bfloat162float(hi2.y);
        __nv_bfloat162 lo2 = __floats2bfloat162_rn(l0, l1);
        lo_st[t] = *(uint32_t*)&lo2;
    }
    __syncthreads();   // all W1 reads complete before overwrite
    #pragma unroll
    for (int t = 0; t < 16; t++) {
        const int idx = tid + 256 * t;
        const int k = idx >> 6, hp = idx & 63;
        smemu[O_UL + k * UST + hp] = lo_st[t];
    }
    __syncthreads();

    // ---------------- GEMM B: jac = SLOPE*S + RCOEF*(mask @ u)  (bf16 hi+lo, k16) -------
    const int nblk2 = (w & 3) * 32;
    const int kblk  = (w >> 2) * 32;

    float acc2[2][4][4];
    #pragma unroll
    for (int i = 0; i < 2; i++)
        #pragma unroll
        for (int j = 0; j < 4; j++)
            #pragma unroll
            for (int q = 0; q < 4; q++) acc2[i][j][q] = 0.0f;

    #pragma unroll 2
    for (int step = 0; step < 8; step++) {
        const int mw    = step >> 1;
        const int shift = (step & 1) * 16 + 2 * lc;
        uint32_t a[2][4];
        #pragma unroll
        for (int i = 0; i < 2; i++) {
            const uint32_t mLo = smemu[O_MASK + (nblk2 + 16 * i + lr) * 4 + mw];
            const uint32_t mHi = smemu[O_MASK + (nblk2 + 16 * i + lr + 8) * 4 + mw];
            a[i][0] = mask2bf((mLo >> shift) & 3u);
            a[i][1] = mask2bf((mHi >> shift) & 3u);
            a[i][2] = mask2bf((mLo >> (shift + 8)) & 3u);
            a[i][3] = mask2bf((mHi >> (shift + 8)) & 3u);
        }
        const int hp0 = 8 * step + lc;
        #pragma unroll
        for (int j = 0; j < 4; j++) {
            const int kp = kblk + 8 * j + lr;
            const uint32_t bh0 = smemu[O_UH + kp * UST + hp0];
            const uint32_t bh1 = smemu[O_UH + kp * UST + hp0 + 4];
            const uint32_t bl0 = smemu[O_UL + kp * UST + hp0];
            const uint32_t bl1 = smemu[O_UL + kp * UST + hp0 + 4];
            #pragma unroll
            for (int i = 0; i < 2; i++) {
                mma16bf(acc2[i][j], a[i], bh0, bh1);
                mma16bf(acc2[i][j], a[i], bl0, bl1);
            }
        }
    }

    // write hist_jac: jac = SLOPE*S[k] + RCOEF*acc2
    #pragma unroll
    for (int i = 0; i < 2; i++) {
        #pragma unroll
        for (int ci = 0; ci < 2; ci++) {
            const int r = nblk2 + 16 * i + 8 * ci + lr;
            float* hb2 = out + HIST_OFF + ((size_t)d * NTOT + n0 + r) * 64;
            #pragma unroll
            for (int j = 0; j < 4; j++) {
                const int col = kblk + 8 * j + 2 * lc;
                const float s0 = sf[O_S + col];
                const float s1 = sf[O_S + col + 1];
                float2 v = make_float2(fmaf(RCOEF, acc2[i][j][2 * ci],     SLOPE * s0),
                                       fmaf(RCOEF, acc2[i][j][2 * ci + 1], SLOPE * s1));
                *(float2*)(hb2 + col) = v;
            }
        }
    }

    __syncthreads();
    if (tid == 0) atomicAdd(&out[SUM_OFF + bb], sf[O_RED]);
}

extern "C" void kernel_launch(void* const* d_in, const int* in_sizes, int n_in,
                              void* d_out, int out_size) {
    const float* x  = (const float*)d_in[0];
    const float* W1 = (const float*)d_in[1];
    const float* b1 = (const float*)d_in[2];
    const float* W2 = (const float*)d_in[3];
    const float* b2 = (const float*)d_in[4];
    float* out = (float*)d_out;

    cudaFuncSetAttribute(fused_mma, cudaFuncAttributeMaxDynamicSharedMemorySize, SMEM_BYTES);

    zero_sum_kernel<<<1, Bb>>>(out);
    fused_mma<<<dim3(Dd, NTILES), 256, SMEM_BYTES>>>(x, W1, b1, W2, b2, out);
}